// round 4
// baseline (speedup 1.0000x reference)
#include <cuda_runtime.h>
#include <math.h>
#include <stdint.h>

#define NNODE   512
#define KPAD    208
#define ROWS_ENC (128*512)   // 65536
#define ROWS_DEC (64*512)    // 32768
#define QW      136          // dense Q row width: [Q1(68)|Q2(68)]
#define INV_S2  0.70710678118654752440f

// ---------------- scratch (device globals; no allocation) ----------------
__device__ __align__(16) float g_MM[1024*512];       // [M1;M2]
__device__ __align__(16) float g_P[512*512];
__device__ float g_rs[512];
__device__ __align__(16) float g_Q[ROWS_ENC*QW];     // diffusion outputs
__device__ __align__(16) float g_H[ROWS_ENC*64];     // encoder H (D: rows<32768, A: rows>=32768)
__device__ __align__(16) float g_Hdec[ROWS_DEC*64];
__device__ __align__(16) float g_z[ROWS_ENC*64];
__device__ __align__(16) float g_r[ROWS_ENC*64];
__device__ __align__(16) float g_xt_enc[6*ROWS_ENC*4];
__device__ __align__(16) float g_xt_dec[ROWS_DEC*4];
__device__ float g_tod[64*12];
__device__ __align__(16) float g_Wzr[3][KPAD*128];   // rows 204..207 stay zero
__device__ float g_bzr[3][128];
__device__ __align__(16) float g_Wc[3][KPAD*64];
__device__ float g_bc[3][64];
__device__ __align__(16) float g_Wmix[128*64];
__device__ float g_bmix[64];

// ---------------- tf32 mma helpers ----------------
__device__ __forceinline__ uint32_t f2tf(float x) {
    uint32_t r;
    asm("cvt.rna.tf32.f32 %0, %1;" : "=r"(r) : "f"(x));
    return r;
}
__device__ __forceinline__ void mma_tf32(float* d, const uint32_t* a, const uint32_t* b) {
    asm volatile(
        "mma.sync.aligned.m16n8k8.row.col.f32.tf32.tf32.f32 "
        "{%0,%1,%2,%3}, {%4,%5,%6,%7}, {%8,%9}, {%0,%1,%2,%3};"
        : "+f"(d[0]), "+f"(d[1]), "+f"(d[2]), "+f"(d[3])
        : "r"(a[0]), "r"(a[1]), "r"(a[2]), "r"(a[3]), "r"(b[0]), "r"(b[1]));
}
__device__ __forceinline__ float sigm(float x) {
    return 1.f / (1.f + __expf(-x));
}

// ---------------- prep ----------------
__global__ void k_rowsum(const float* __restrict__ A) {
    int v = blockIdx.x;
    float s = 0.f;
    for (int w = threadIdx.x; w < 512; w += 128) s += A[v*512+w];
    __shared__ float sh[128];
    sh[threadIdx.x] = s; __syncthreads();
    for (int o = 64; o > 0; o >>= 1) {
        if (threadIdx.x < o) sh[threadIdx.x] += sh[threadIdx.x+o];
        __syncthreads();
    }
    if (threadIdx.x == 0) g_rs[v] = sh[0] + 1.0f;
}

__global__ void k_P(const float* __restrict__ A) {
    int idx = blockIdx.x*blockDim.x + threadIdx.x;
    if (idx >= 512*512) return;
    int w = idx >> 9, v = idx & 511;
    float a  = A[v*512+w];
    float an = (a + (v==w ? 1.f : 0.f)) / g_rs[v];
    float p  = 0.95f*an + 0.95f*a;
    g_P[w*512+v]  = p;
    g_MM[w*512+v] = (v==w ? 0.05f : 0.f) + p;             // M1 = aI + P
}

__global__ void k_M2() {
    int idx = blockIdx.x*blockDim.x + threadIdx.x;
    if (idx >= 512*512) return;
    int w = idx >> 9, v = idx & 511;
    const float* pw = g_P + w*512;
    float s = 0.f;
    #pragma unroll 8
    for (int u = 0; u < 512; u++) s += pw[u] * g_P[u*512+v];
    g_MM[(512+w)*512+v] = (w==v ? 0.05f : 0.f) + 0.05f*g_P[w*512+v] + s;  // M2
}

__global__ void k_weights(const float* __restrict__ Wg, const float* __restrict__ bg) {
    int idx = blockIdx.x*blockDim.x + threadIdx.x;
    const int TZR = 3*204*128, TC = 3*204*64;
    if (idx < TZR) {
        int p = idx / (204*128); int rem = idx % (204*128);
        int k = rem / 128, g = rem % 128;
        int gate = (g < 64) ? 0 : 2;  int c = g & 63;
        int w1 = 6*p + gate;
        g_Wzr[p][k*128+g] = Wg[(w1*204+k)*64+c] + Wg[((w1+1)*204+k)*64+c];
    } else if (idx < TZR + TC) {
        int j = idx - TZR;
        int p = j / (204*64); int rem = j % (204*64);
        int k = rem / 64, c = rem % 64;
        int w1 = 6*p + 4;
        g_Wc[p][k*64+c] = Wg[(w1*204+k)*64+c] + Wg[((w1+1)*204+k)*64+c];
    } else if (idx < TZR + TC + 3*128) {
        int j = idx - TZR - TC;
        int p = j / 128, g = j % 128;
        int gate = (g < 64) ? 0 : 2; int c = g & 63;
        g_bzr[p][g] = bg[(6*p+gate)*64+c] + bg[(6*p+gate+1)*64+c];
    } else if (idx < TZR + TC + 3*128 + 3*64) {
        int j = idx - TZR - TC - 3*128;
        int p = j / 64, c = j % 64;
        g_bc[p][c] = bg[(6*p+4)*64+c] + bg[(6*p+5)*64+c];
    }
}

__global__ void k_mixw(const float* __restrict__ Wi, const float* __restrict__ bi,
                       const float* __restrict__ Wm, const float* __restrict__ bm) {
    int idx = blockIdx.x*blockDim.x + threadIdx.x;
    if (idx < 4096) {
        int k = idx >> 6, c = idx & 63;
        float s = 0.f;
        for (int j = 0; j < 64; j++) {
            s += Wi[k*64+j]        * Wm[(256+2*j  )*64+c]
               + Wi[4096 + k*64+j] * Wm[(256+2*j+1)*64+c];
        }
        g_Wmix[k*64+c]        = 0.3f*s + 0.7f*Wm[(128+k)*64+c];
        g_Wmix[(64+k)*64+c]   = 0.3f*s + 0.7f*Wm[(128+64+k)*64+c];
    } else if (idx < 4096 + 64) {
        int c = idx - 4096;
        float s = 0.f;
        for (int j = 0; j < 64; j++)
            s += 2.f*bi[j]    * Wm[(256+2*j  )*64+c]
               + 2.f*bi[64+j] * Wm[(256+2*j+1)*64+c];
        g_bmix[c] = 0.3f*(s + bm[128+c]) + 0.7f*bm[64+c];
    }
}

__global__ void k_tod(const float* __restrict__ st) {
    int idx = blockIdx.x*blockDim.x + threadIdx.x;
    if (idx >= 64*12) return;
    int b = idx / 12, t = idx % 12;
    g_tod[idx] = (float)(int)((st[(b*5+2)*12+t] + 0.5f) * 6.0f);
}

__global__ void k_xt_enc(const float* __restrict__ x, const float* __restrict__ st) {
    int idx = blockIdx.x*blockDim.x + threadIdx.x;
    if (idx >= 6*ROWS_ENC*4) return;
    int c   = idx & 3;
    int rem = idx >> 2;
    int row = rem & (ROWS_ENC-1);
    int t   = rem >> 16;           // ROWS_ENC = 65536
    int bp = row >> 9, n = row & 511;
    int b = bp & 63;
    float val;
    if (c < 3) {
        float xe = x[((b*3+c)*512+n)*12 + 2*t];
        float xo = x[((b*3+c)*512+n)*12 + 2*t + 1];
        val = ((bp < 64) ? (xe - xo) : (xe + xo)) * INV_S2;
    } else {
        int s = 2*t;
        float hour   = (st[(b*5+3)*12+s] + 0.5f) * 23.0f;
        float minute = (st[(b*5+4)*12+s] + 0.5f) * 59.0f;
        val = (float)(int)((hour*60.0f + minute) / 5.0f);
    }
    g_xt_enc[idx] = val;
}

__global__ void k_init_state() {
    int idx = blockIdx.x*blockDim.x + threadIdx.x;
    if (idx < ROWS_ENC*64) { g_H[idx] = 0.f; return; }
    int j = idx - ROWS_ENC*64;
    if (j < ROWS_DEC*4) {
        int c = j & 3; int row = j >> 2; int b = row >> 9;
        g_xt_dec[j] = (c < 3) ? 0.f : g_tod[b*12 + 0];
    }
}

// ---------------- fused TF32 diffusion GEMM ----------------
// Q[:, :] = [M1;M2] @ B  where B[v,(bp,c)] = c<4 ? xt : (pass? r*H : H)
__global__ void __launch_bounds__(256) k_graph_f(int t, int dec, int pass) {
    const int j0 = blockIdx.x * 128;
    const int m0 = blockIdx.y * 128;
    __shared__ uint32_t As[2][128][20];
    __shared__ uint32_t Bs[2][128][20];
    __shared__ int qoff[128];
    const int tid = threadIdx.x;
    const int bn = tid & 127;

    const int j = j0 + bn;
    const int bp = j / 68, c = j % 68;
    if (tid < 128) qoff[tid] = bp*512*QW + c;
    const float* xt = dec ? g_xt_dec : (g_xt_enc + (size_t)t*ROWS_ENC*4);
    const float* Hp = dec ? g_Hdec : g_H;
    const float* s1; const float* s2 = 0; int st;
    const int row0 = bp*512;
    if (c < 4) { s1 = xt + (size_t)row0*4 + c; st = 4; }
    else {
        s1 = Hp + (size_t)row0*64 + (c-4); st = 64;
        if (pass) s2 = g_r + (size_t)row0*64 + (c-4);
    }
    __syncthreads();

    const int lane = tid & 31, wid = tid >> 5;
    const int wm = wid & 1, wn = wid >> 1;        // 2 m-warps x 4 n-warps (64x32)
    const int g = lane >> 2, t4 = lane & 3;
    float C[4][4][4];
    #pragma unroll
    for (int i = 0; i < 4; i++)
        #pragma unroll
        for (int jj = 0; jj < 4; jj++)
            #pragma unroll
            for (int r = 0; r < 4; r++) C[i][jj][r] = 0.f;

    const int bk0 = (tid >> 7) * 8;
    float4 avr[2]; float bvr[8];

    // prologue: stage tile 0
    {
        const int k0 = 0;
        #pragma unroll
        for (int s = 0; s < 2; s++) {
            int i = tid + s*256;
            avr[s] = *(const float4*)&g_MM[(m0 + (i>>2))*512 + k0 + (i&3)*4];
        }
        #pragma unroll
        for (int i = 0; i < 8; i++) {
            int v = k0 + bk0 + i;
            bvr[i] = s2 ? s1[(size_t)v*64]*s2[(size_t)v*64] : s1[(size_t)v*st];
        }
        #pragma unroll
        for (int s = 0; s < 2; s++) {
            int i = tid + s*256;
            int r = i>>2, kq = (i&3)*4;
            As[0][r][kq+0] = f2tf(avr[s].x); As[0][r][kq+1] = f2tf(avr[s].y);
            As[0][r][kq+2] = f2tf(avr[s].z); As[0][r][kq+3] = f2tf(avr[s].w);
        }
        #pragma unroll
        for (int i = 0; i < 8; i++) Bs[0][bn][bk0+i] = f2tf(bvr[i]);
    }
    __syncthreads();

    for (int kt = 0; kt < 32; kt++) {
        const int cur = kt & 1;
        if (kt < 31) {
            const int k0 = (kt+1)*16;
            #pragma unroll
            for (int s = 0; s < 2; s++) {
                int i = tid + s*256;
                avr[s] = *(const float4*)&g_MM[(m0 + (i>>2))*512 + k0 + (i&3)*4];
            }
            #pragma unroll
            for (int i = 0; i < 8; i++) {
                int v = k0 + bk0 + i;
                bvr[i] = s2 ? s1[(size_t)v*64]*s2[(size_t)v*64] : s1[(size_t)v*st];
            }
        }
        #pragma unroll
        for (int kc = 0; kc < 16; kc += 8) {
            uint32_t a[4][4], b[4][2];
            #pragma unroll
            for (int mi = 0; mi < 4; mi++) {
                int m = wm*64 + mi*16 + g;
                a[mi][0] = As[cur][m][kc + t4];
                a[mi][1] = As[cur][m + 8][kc + t4];
                a[mi][2] = As[cur][m][kc + t4 + 4];
                a[mi][3] = As[cur][m + 8][kc + t4 + 4];
            }
            #pragma unroll
            for (int ni = 0; ni < 4; ni++) {
                int n = wn*32 + ni*8 + g;
                b[ni][0] = Bs[cur][n][kc + t4];
                b[ni][1] = Bs[cur][n][kc + t4 + 4];
            }
            #pragma unroll
            for (int mi = 0; mi < 4; mi++)
                #pragma unroll
                for (int ni = 0; ni < 4; ni++)
                    mma_tf32(C[mi][ni], a[mi], b[ni]);
        }
        if (kt < 31) {
            const int nxt = cur ^ 1;
            #pragma unroll
            for (int s = 0; s < 2; s++) {
                int i = tid + s*256;
                int r = i>>2, kq = (i&3)*4;
                As[nxt][r][kq+0] = f2tf(avr[s].x); As[nxt][r][kq+1] = f2tf(avr[s].y);
                As[nxt][r][kq+2] = f2tf(avr[s].z); As[nxt][r][kq+3] = f2tf(avr[s].w);
            }
            #pragma unroll
            for (int i = 0; i < 8; i++) Bs[nxt][bn][bk0+i] = f2tf(bvr[i]);
        }
        __syncthreads();
    }
    #pragma unroll
    for (int mi = 0; mi < 4; mi++) {
        #pragma unroll
        for (int rr = 0; rr < 2; rr++) {
            int m = m0 + wm*64 + mi*16 + g + rr*8;
            int node  = m & 511;
            int which = m >> 9;
            size_t rbase = (size_t)node * QW + which * 68;
            #pragma unroll
            for (int ni = 0; ni < 4; ni++) {
                int n = wn*32 + ni*8 + 2*t4;
                g_Q[qoff[n]   + rbase] = C[mi][ni][rr*2+0];
                g_Q[qoff[n+1] + rbase] = C[mi][ni][rr*2+1];
            }
        }
    }
}

// ---------------- fused TF32 zr gate: [Z|R] = sigmoid([xt|H|Q] @ Wzr + b) ----------------
__global__ void __launch_bounds__(256) k_gatezr_f(int t, int dec) {
    const int r0 = blockIdx.x * 128;
    const int p = dec ? 2 : ((r0 < ROWS_DEC) ? 0 : 1);
    __shared__ uint32_t As[2][128][20];
    __shared__ uint32_t Bs[2][128][20];
    const int tid = threadIdx.x;
    const float* xt = dec ? g_xt_dec : (g_xt_enc + (size_t)t*ROWS_ENC*4);
    const float* Hp = dec ? g_Hdec : g_H;
    const float* Wp = g_Wzr[p];

    const int lane = tid & 31, wid = tid >> 5;
    const int wm = wid & 1, wn = wid >> 1;
    const int g = lane >> 2, t4 = lane & 3;
    float C[4][4][4];
    #pragma unroll
    for (int i = 0; i < 4; i++)
        #pragma unroll
        for (int jj = 0; jj < 4; jj++)
            #pragma unroll
            for (int r = 0; r < 4; r++) C[i][jj][r] = 0.f;

    const int bn = tid & 127, bk0 = (tid >> 7) * 8;
    float4 avr[2]; float bvr[8];

    #define LOAD_A_ZR(k0) \
        _Pragma("unroll") \
        for (int s = 0; s < 2; s++) { \
            int i = tid + s*256; \
            int row = r0 + (i>>2); \
            int k = (k0) + (i&3)*4; \
            float4 v; \
            if (k < 4)        v = *(const float4*)&xt[(size_t)row*4]; \
            else if (k < 68)  v = *(const float4*)&Hp[(size_t)row*64 + k-4]; \
            else if (k < 204) v = *(const float4*)&g_Q[(size_t)row*QW + k-68]; \
            else              v = make_float4(0.f,0.f,0.f,0.f); \
            avr[s] = v; \
        }
    #define LOAD_B_ZR(k0) \
        _Pragma("unroll") \
        for (int i = 0; i < 8; i++) bvr[i] = Wp[((k0)+bk0+i)*128 + bn];
    #define STORE_ST(buf) \
        _Pragma("unroll") \
        for (int s = 0; s < 2; s++) { \
            int i = tid + s*256; \
            int r = i>>2, kq = (i&3)*4; \
            As[buf][r][kq+0] = f2tf(avr[s].x); As[buf][r][kq+1] = f2tf(avr[s].y); \
            As[buf][r][kq+2] = f2tf(avr[s].z); As[buf][r][kq+3] = f2tf(avr[s].w); \
        } \
        _Pragma("unroll") \
        for (int i = 0; i < 8; i++) Bs[buf][bn][bk0+i] = f2tf(bvr[i]);

    LOAD_A_ZR(0); LOAD_B_ZR(0); STORE_ST(0);
    __syncthreads();

    for (int kt = 0; kt < 13; kt++) {
        const int cur = kt & 1;
        if (kt < 12) { int k0n = (kt+1)*16; LOAD_A_ZR(k0n); LOAD_B_ZR(k0n); }
        #pragma unroll
        for (int kc = 0; kc < 16; kc += 8) {
            uint32_t a[4][4], b[4][2];
            #pragma unroll
            for (int mi = 0; mi < 4; mi++) {
                int m = wm*64 + mi*16 + g;
                a[mi][0] = As[cur][m][kc + t4];
                a[mi][1] = As[cur][m + 8][kc + t4];
                a[mi][2] = As[cur][m][kc + t4 + 4];
                a[mi][3] = As[cur][m + 8][kc + t4 + 4];
            }
            #pragma unroll
            for (int ni = 0; ni < 4; ni++) {
                int n = wn*32 + ni*8 + g;
                b[ni][0] = Bs[cur][n][kc + t4];
                b[ni][1] = Bs[cur][n][kc + t4 + 4];
            }
            #pragma unroll
            for (int mi = 0; mi < 4; mi++)
                #pragma unroll
                for (int ni = 0; ni < 4; ni++)
                    mma_tf32(C[mi][ni], a[mi], b[ni]);
        }
        if (kt < 12) { STORE_ST(cur ^ 1); }
        __syncthreads();
    }
    #pragma unroll
    for (int mi = 0; mi < 4; mi++) {
        #pragma unroll
        for (int rr = 0; rr < 2; rr++) {
            int row = r0 + wm*64 + mi*16 + g + rr*8;
            #pragma unroll
            for (int ni = 0; ni < 4; ni++) {
                #pragma unroll
                for (int q = 0; q < 2; q++) {
                    int col = wn*32 + ni*8 + 2*t4 + q;
                    float v = sigm(C[mi][ni][rr*2+q] + g_bzr[p][col]);
                    if (col < 64) g_z[(size_t)row*64 + col]      = v;
                    else          g_r[(size_t)row*64 + col - 64] = v;
                }
            }
        }
    }
    #undef LOAD_A_ZR
    #undef LOAD_B_ZR
    #undef STORE_ST
}

// ---------------- fused TF32 C gate + H update: H = z*H + (1-z)*tanh([xt|r*H|Q]@Wc+b) ----------------
__global__ void __launch_bounds__(256) k_gatec_f(int t, int dec) {
    const int r0 = blockIdx.x * 128;
    const int p = dec ? 2 : ((r0 < ROWS_DEC) ? 0 : 1);
    float* H = dec ? g_Hdec : g_H;
    __shared__ uint32_t As[2][128][20];
    __shared__ uint32_t Bs[2][64][20];
    const int tid = threadIdx.x;
    const float* xt = dec ? g_xt_dec : (g_xt_enc + (size_t)t*ROWS_ENC*4);
    const float* Wp = g_Wc[p];

    const int lane = tid & 31, wid = tid >> 5;
    const int wm = wid & 3, wn = wid >> 2;        // 4 m-warps x 2 n-warps (32x32)
    const int g = lane >> 2, t4 = lane & 3;
    float C[2][4][4];
    #pragma unroll
    for (int i = 0; i < 2; i++)
        #pragma unroll
        for (int jj = 0; jj < 4; jj++)
            #pragma unroll
            for (int r = 0; r < 4; r++) C[i][jj][r] = 0.f;

    const int bn = tid & 63, bk0 = (tid >> 6) * 4;
    float4 avr[2]; float bvr[4];

    #define LOAD_A_C(k0) \
        _Pragma("unroll") \
        for (int s = 0; s < 2; s++) { \
            int i = tid + s*256; \
            int row = r0 + (i>>2); \
            int k = (k0) + (i&3)*4; \
            float4 v; \
            if (k < 4)        v = *(const float4*)&xt[(size_t)row*4]; \
            else if (k < 68) { \
                float4 h = *(const float4*)&H[(size_t)row*64 + k-4]; \
                float4 rr4 = *(const float4*)&g_r[(size_t)row*64 + k-4]; \
                v = make_float4(h.x*rr4.x, h.y*rr4.y, h.z*rr4.z, h.w*rr4.w); \
            } \
            else if (k < 204) v = *(const float4*)&g_Q[(size_t)row*QW + k-68]; \
            else              v = make_float4(0.f,0.f,0.f,0.f); \
            avr[s] = v; \
        }
    #define LOAD_B_C(k0) \
        _Pragma("unroll") \
        for (int i = 0; i < 4; i++) bvr[i] = Wp[((k0)+bk0+i)*64 + bn];
    #define STORE_ST_C(buf) \
        _Pragma("unroll") \
        for (int s = 0; s < 2; s++) { \
            int i = tid + s*256; \
            int r = i>>2, kq = (i&3)*4; \
            As[buf][r][kq+0] = f2tf(avr[s].x); As[buf][r][kq+1] = f2tf(avr[s].y); \
            As[buf][r][kq+2] = f2tf(avr[s].z); As[buf][r][kq+3] = f2tf(avr[s].w); \
        } \
        _Pragma("unroll") \
        for (int i = 0; i < 4; i++) Bs[buf][bn][bk0+i] = f2tf(bvr[i]);

    LOAD_A_C(0); LOAD_B_C(0); STORE_ST_C(0);
    __syncthreads();

    for (int kt = 0; kt < 13; kt++) {
        const int cur = kt & 1;
        if (kt < 12) { int k0n = (kt+1)*16; LOAD_A_C(k0n); LOAD_B_C(k0n); }
        #pragma unroll
        for (int kc = 0; kc < 16; kc += 8) {
            uint32_t a[2][4], b[4][2];
            #pragma unroll
            for (int mi = 0; mi < 2; mi++) {
                int m = wm*32 + mi*16 + g;
                a[mi][0] = As[cur][m][kc + t4];
                a[mi][1] = As[cur][m + 8][kc + t4];
                a[mi][2] = As[cur][m][kc + t4 + 4];
                a[mi][3] = As[cur][m + 8][kc + t4 + 4];
            }
            #pragma unroll
            for (int ni = 0; ni < 4; ni++) {
                int n = wn*32 + ni*8 + g;
                b[ni][0] = Bs[cur][n][kc + t4];
                b[ni][1] = Bs[cur][n][kc + t4 + 4];
            }
            #pragma unroll
            for (int mi = 0; mi < 2; mi++)
                #pragma unroll
                for (int ni = 0; ni < 4; ni++)
                    mma_tf32(C[mi][ni], a[mi], b[ni]);
        }
        if (kt < 12) { STORE_ST_C(cur ^ 1); }
        __syncthreads();
    }
    #pragma unroll
    for (int mi = 0; mi < 2; mi++) {
        #pragma unroll
        for (int rr = 0; rr < 2; rr++) {
            int row = r0 + wm*32 + mi*16 + g + rr*8;
            #pragma unroll
            for (int ni = 0; ni < 4; ni++) {
                #pragma unroll
                for (int q = 0; q < 2; q++) {
                    int col = wn*32 + ni*8 + 2*t4 + q;
                    float c = tanhf(C[mi][ni][rr*2+q] + g_bc[p][col]);
                    float z = g_z[(size_t)row*64 + col];
                    float h = H[(size_t)row*64 + col];
                    H[(size_t)row*64 + col] = z*h + (1.f - z)*c;
                }
            }
        }
    }
    #undef LOAD_A_C
    #undef LOAD_B_C
    #undef STORE_ST_C
}

// ---------------- mix GEMM (fp32, one call): Hdec = H1@WmA + H2@WmB + bmix ----------------
__global__ void __launch_bounds__(256) k_mix() {
    const int r0 = blockIdx.x * 128;
    __shared__ float As[8][128];
    __shared__ float Bs[8][64];
    const int tid = threadIdx.x;
    float acc[8][4];
    #pragma unroll
    for (int i = 0; i < 8; i++)
        #pragma unroll
        for (int j = 0; j < 4; j++) acc[i][j] = 0.f;

    const int arow = tid >> 1, acol = (tid & 1) * 4;
    const int tx = tid & 15, ty = tid >> 4;

    for (int k0 = 0; k0 < 128; k0 += 8) {
        int row = r0 + arow;
        const float* src = (k0 < 64) ? &g_H[(size_t)row*64 + k0 + acol]
                                     : &g_H[((size_t)row + ROWS_DEC)*64 + (k0 - 64) + acol];
        float4 av = *(const float4*)src;
        As[acol+0][arow] = av.x; As[acol+1][arow] = av.y;
        As[acol+2][arow] = av.z; As[acol+3][arow] = av.w;
        #pragma unroll
        for (int r = 0; r < 2; r++) {
            int ii = tid + r*256;
            int k = ii >> 6, j = ii & 63;
            Bs[k][j] = g_Wmix[(k0+k)*64 + j];
        }
        __syncthreads();
        #pragma unroll
        for (int kk = 0; kk < 8; kk++) {
            float4 a0 = *(const float4*)&As[kk][ty*8];
            float4 a1 = *(const float4*)&As[kk][ty*8+4];
            float4 b0 = *(const float4*)&Bs[kk][tx*4];
            float aa[8] = {a0.x,a0.y,a0.z,a0.w,a1.x,a1.y,a1.z,a1.w};
            float bb[4] = {b0.x,b0.y,b0.z,b0.w};
            #pragma unroll
            for (int i = 0; i < 8; i++)
                #pragma unroll
                for (int j = 0; j < 4; j++)
                    acc[i][j] += aa[i]*bb[j];
        }
        __syncthreads();
    }
    #pragma unroll
    for (int i = 0; i < 8; i++) {
        int row = r0 + ty*8 + i;
        #pragma unroll
        for (int j = 0; j < 4; j++) {
            int col = tx*4 + j;
            g_Hdec[row*64 + col] = acc[i][j] + g_bmix[col];
        }
    }
}

// ---------------- decoder FC + output scatter + next xt ----------------
__global__ void k_fc(const float* __restrict__ Wfc, const float* __restrict__ bfc,
                     float* __restrict__ out, int t) {
    int row = blockIdx.x*blockDim.x + threadIdx.x;
    if (row >= ROWS_DEC) return;
    int b = row >> 9, n = row & 511;
    float a0 = bfc[0], a1 = bfc[1], a2 = bfc[2];
    const float* h = &g_Hdec[(size_t)row*64];
    #pragma unroll 8
    for (int k = 0; k < 64; k++) {
        float hv = h[k];
        a0 += hv * Wfc[k*3+0];
        a1 += hv * Wfc[k*3+1];
        a2 += hv * Wfc[k*3+2];
    }
    float av[3] = {a0, a1, a2};
    #pragma unroll
    for (int d = 0; d < 3; d++) {
        int L = 3*t + d;
        int dp = L / 12, tp = L % 12;
        out[((b*3+dp)*512 + n)*12 + tp] = av[d];
        g_xt_dec[row*4 + d] = av[d];
    }
    if (t + 1 < 12) g_xt_dec[row*4 + 3] = g_tod[b*12 + t + 1];
}

// ---------------- launch ----------------
extern "C" void kernel_launch(void* const* d_in, const int* in_sizes, int n_in,
                              void* d_out, int out_size) {
    const float* x   = (const float*)d_in[0];
    const float* st  = (const float*)d_in[2];
    const float* A   = (const float*)d_in[3];
    const float* Wg  = (const float*)d_in[4];
    const float* bg  = (const float*)d_in[5];
    const float* Wm  = (const float*)d_in[6];
    const float* bm  = (const float*)d_in[7];
    const float* Wi  = (const float*)d_in[8];
    const float* bi  = (const float*)d_in[9];
    const float* Wfc = (const float*)d_in[10];
    const float* bfc = (const float*)d_in[11];
    float* out = (float*)d_out;

    // prep
    k_rowsum<<<512, 128>>>(A);
    k_P<<<1024, 256>>>(A);
    k_M2<<<1024, 256>>>();
    k_weights<<<(3*204*128 + 3*204*64 + 3*128 + 3*64 + 255)/256, 256>>>(Wg, bg);
    k_mixw<<<(4160 + 255)/256, 256>>>(Wi, bi, Wm, bm);
    k_tod<<<3, 256>>>(st);
    k_xt_enc<<<(6*ROWS_ENC*4)/256, 256>>>(x, st);
    k_init_state<<<(ROWS_ENC*64 + ROWS_DEC*4)/256, 256>>>();

    // encoders (D + A batched: 128 batch-slices)
    for (int t = 0; t < 6; t++) {
        k_graph_f<<<dim3(68, 8), 256>>>(t, 0, 0);
        k_gatezr_f<<<ROWS_ENC/128, 256>>>(t, 0);
        k_graph_f<<<dim3(68, 8), 256>>>(t, 0, 1);
        k_gatec_f<<<ROWS_ENC/128, 256>>>(t, 0);
    }

    // mix -> decoder initial H
    k_mix<<<ROWS_DEC/128, 256>>>();

    // decoder
    for (int t = 0; t < 12; t++) {
        k_graph_f<<<dim3(34, 8), 256>>>(0, 1, 0);
        k_gatezr_f<<<ROWS_DEC/128, 256>>>(0, 1);
        k_graph_f<<<dim3(34, 8), 256>>>(0, 1, 1);
        k_gatec_f<<<ROWS_DEC/128, 256>>>(0, 1);
        k_fc<<<ROWS_DEC/256, 256>>>(Wfc, bfc, out, t);
    }
}

// round 6
// speedup vs baseline: 1.3265x; 1.3265x over previous
#include <cuda_runtime.h>
#include <cuda_fp16.h>
#include <math.h>
#include <stdint.h>

#define NNODE   512
#define KPAD    208
#define ROWS_ENC (128*512)   // 65536
#define ROWS_DEC (64*512)    // 32768
#define BSTRIDE  (512*KPAD)
#define INV_S2  0.70710678118654752440f

// ---------------- scratch (device globals; no allocation) ----------------
__device__ __align__(16) __half g_MMh[1024*512];      // [M1;M2] fp16
__device__ __align__(16) float  g_P[512*512];
__device__ float g_rs[512];
__device__ __align__(16) __half g_CATh[ROWS_ENC*KPAD]; // [comb(68)|Q1(68)|Q2(68)|pad(4)=0]
__device__ __align__(16) float g_H[ROWS_ENC*64];
__device__ __align__(16) float g_Hdec[ROWS_DEC*64];
__device__ __align__(16) float g_z[ROWS_ENC*64];
__device__ __align__(16) float g_r[ROWS_ENC*64];
__device__ __align__(16) float g_xt_enc[6*ROWS_ENC*4];
__device__ __align__(16) float g_xt_dec[ROWS_DEC*4];
__device__ float g_tod[64*12];
__device__ __align__(16) __half g_Wzrh[3][KPAD*128];  // rows 204..207 stay zero (bss zero-init)
__device__ float g_bzr[3][128];
__device__ __align__(16) __half g_Wch[3][KPAD*64];
__device__ float g_bc[3][64];
__device__ __align__(16) float g_Wmix[128*64];
__device__ float g_bmix[64];

// ---------------- fp16 mma helper ----------------
__device__ __forceinline__ void mma_f16(float* d, const uint32_t* a, const uint32_t* b) {
    asm volatile(
        "mma.sync.aligned.m16n8k16.row.col.f32.f16.f16.f32 "
        "{%0,%1,%2,%3}, {%4,%5,%6,%7}, {%8,%9}, {%0,%1,%2,%3};"
        : "+f"(d[0]), "+f"(d[1]), "+f"(d[2]), "+f"(d[3])
        : "r"(a[0]), "r"(a[1]), "r"(a[2]), "r"(a[3]), "r"(b[0]), "r"(b[1]));
}
__device__ __forceinline__ float sigm(float x) { return 1.f / (1.f + __expf(-x)); }

// ---------------- prep ----------------
__global__ void k_rowsum(const float* __restrict__ A) {
    int v = blockIdx.x;
    float s = 0.f;
    for (int w = threadIdx.x; w < 512; w += 128) s += A[v*512+w];
    __shared__ float sh[128];
    sh[threadIdx.x] = s; __syncthreads();
    for (int o = 64; o > 0; o >>= 1) {
        if (threadIdx.x < o) sh[threadIdx.x] += sh[threadIdx.x+o];
        __syncthreads();
    }
    if (threadIdx.x == 0) g_rs[v] = sh[0] + 1.0f;
}

__global__ void k_P(const float* __restrict__ A) {
    int idx = blockIdx.x*blockDim.x + threadIdx.x;
    if (idx >= 512*512) return;
    int w = idx >> 9, v = idx & 511;
    float a  = A[v*512+w];
    float an = (a + (v==w ? 1.f : 0.f)) / g_rs[v];
    float p  = 0.95f*an + 0.95f*a;
    g_P[w*512+v]   = p;
    g_MMh[w*512+v] = __float2half_rn((v==w ? 0.05f : 0.f) + p);   // M1
}

__global__ void k_M2() {
    int idx = blockIdx.x*blockDim.x + threadIdx.x;
    if (idx >= 512*512) return;
    int w = idx >> 9, v = idx & 511;
    const float* pw = g_P + w*512;
    float s = 0.f;
    #pragma unroll 8
    for (int u = 0; u < 512; u++) s += pw[u] * g_P[u*512+v];
    g_MMh[(512+w)*512+v] = __float2half_rn((w==v ? 0.05f : 0.f) + 0.05f*g_P[w*512+v] + s); // M2
}

__global__ void k_weights(const float* __restrict__ Wg, const float* __restrict__ bg) {
    int idx = blockIdx.x*blockDim.x + threadIdx.x;
    const int TZR = 3*204*128, TC = 3*204*64;
    if (idx < TZR) {
        int p = idx / (204*128); int rem = idx % (204*128);
        int k = rem / 128, g = rem % 128;
        int gate = (g < 64) ? 0 : 2;  int c = g & 63;
        int w1 = 6*p + gate;
        g_Wzrh[p][k*128+g] = __float2half_rn(Wg[(w1*204+k)*64+c] + Wg[((w1+1)*204+k)*64+c]);
    } else if (idx < TZR + TC) {
        int j = idx - TZR;
        int p = j / (204*64); int rem = j % (204*64);
        int k = rem / 64, c = rem % 64;
        int w1 = 6*p + 4;
        g_Wch[p][k*64+c] = __float2half_rn(Wg[(w1*204+k)*64+c] + Wg[((w1+1)*204+k)*64+c]);
    } else if (idx < TZR + TC + 3*128) {
        int j = idx - TZR - TC;
        int p = j / 128, g = j % 128;
        int gate = (g < 64) ? 0 : 2; int c = g & 63;
        g_bzr[p][g] = bg[(6*p+gate)*64+c] + bg[(6*p+gate+1)*64+c];
    } else if (idx < TZR + TC + 3*128 + 3*64) {
        int j = idx - TZR - TC - 3*128;
        int p = j / 64, c = j % 64;
        g_bc[p][c] = bg[(6*p+4)*64+c] + bg[(6*p+5)*64+c];
    }
}

__global__ void k_mixw(const float* __restrict__ Wi, const float* __restrict__ bi,
                       const float* __restrict__ Wm, const float* __restrict__ bm) {
    int idx = blockIdx.x*blockDim.x + threadIdx.x;
    if (idx < 4096) {
        int k = idx >> 6, c = idx & 63;
        float s = 0.f;
        for (int j = 0; j < 64; j++) {
            s += Wi[k*64+j]        * Wm[(256+2*j  )*64+c]
               + Wi[4096 + k*64+j] * Wm[(256+2*j+1)*64+c];
        }
        g_Wmix[k*64+c]      = 0.3f*s + 0.7f*Wm[(128+k)*64+c];
        g_Wmix[(64+k)*64+c] = 0.3f*s + 0.7f*Wm[(128+64+k)*64+c];
    } else if (idx < 4096 + 64) {
        int c = idx - 4096;
        float s = 0.f;
        for (int j = 0; j < 64; j++)
            s += 2.f*bi[j]    * Wm[(256+2*j  )*64+c]
               + 2.f*bi[64+j] * Wm[(256+2*j+1)*64+c];
        g_bmix[c] = 0.3f*(s + bm[128+c]) + 0.7f*bm[64+c];
    }
}

__global__ void k_tod(const float* __restrict__ st) {
    int idx = blockIdx.x*blockDim.x + threadIdx.x;
    if (idx >= 64*12) return;
    int b = idx / 12, t = idx % 12;
    g_tod[idx] = (float)(int)((st[(b*5+2)*12+t] + 0.5f) * 6.0f);
}

__global__ void k_xt_enc(const float* __restrict__ x, const float* __restrict__ st) {
    int idx = blockIdx.x*blockDim.x + threadIdx.x;
    if (idx >= 6*ROWS_ENC*4) return;
    int c   = idx & 3;
    int rem = idx >> 2;
    int row = rem & (ROWS_ENC-1);
    int t   = rem >> 16;
    int bp = row >> 9, n = row & 511;
    int b = bp & 63;
    float val;
    if (c < 3) {
        float xe = x[((b*3+c)*512+n)*12 + 2*t];
        float xo = x[((b*3+c)*512+n)*12 + 2*t + 1];
        val = ((bp < 64) ? (xe - xo) : (xe + xo)) * INV_S2;
    } else {
        int s = 2*t;
        float hour   = (st[(b*5+3)*12+s] + 0.5f) * 23.0f;
        float minute = (st[(b*5+4)*12+s] + 0.5f) * 59.0f;
        val = (float)(int)((hour*60.0f + minute) / 5.0f);
    }
    g_xt_enc[idx] = val;
}

__global__ void k_init_state() {
    int idx = blockIdx.x*blockDim.x + threadIdx.x;
    if (idx < ROWS_ENC*64) { g_H[idx] = 0.f; return; }
    int j = idx - ROWS_ENC*64;
    if (j < ROWS_DEC*4) {
        int c = j & 3; int row = j >> 2; int b = row >> 9;
        g_xt_dec[j] = (c < 3) ? 0.f : g_tod[b*12 + 0];
    }
}

// ---------------- per-step elementwise (write half CAT) ----------------
__global__ void k_comb(int t, int dec) {
    int rows = dec ? ROWS_DEC : ROWS_ENC;
    int idx = blockIdx.x*blockDim.x + threadIdx.x;
    if (idx >= rows*68) return;
    int row = idx / 68, c = idx - row*68;
    const float* xt = dec ? g_xt_dec : (g_xt_enc + (size_t)t*ROWS_ENC*4);
    const float* H  = dec ? g_Hdec   : g_H;
    g_CATh[(size_t)row*KPAD + c] = __float2half_rn((c < 4) ? xt[row*4 + c] : H[row*64 + (c-4)]);
}

__global__ void k_temp(int dec) {
    int rows = dec ? ROWS_DEC : ROWS_ENC;
    int idx = blockIdx.x*blockDim.x + threadIdx.x;
    if (idx >= rows*64) return;
    int row = idx >> 6, c = idx & 63;
    const float* H = dec ? g_Hdec : g_H;
    g_CATh[(size_t)row*KPAD + 4 + c] = __float2half_rn(g_r[idx] * H[idx]);
}

// ---------------- FP16 diffusion GEMM: CAT[:,68:204] = [M1;M2] @ CAT[:,0:68] ----------------
__global__ void __launch_bounds__(256) k_graph_h() {
    const int j0 = blockIdx.x * 128;
    const int m0 = blockIdx.y * 128;
    __shared__ __half As[128][24];
    __shared__ __half Bs[128][24];
    __shared__ int coff[128];
    const int tid = threadIdx.x;
    if (tid < 128) {
        int j = j0 + tid;
        coff[tid] = (j / 68) * BSTRIDE + (j % 68);
    }
    __syncthreads();
    const int lane = tid & 31, wid = tid >> 5;
    const int wm = wid & 1, wn = wid >> 1;        // 2 m-warps x 4 n-warps (64x32)
    const int g = lane >> 2, t4 = lane & 3;
    float C[4][4][4];
    #pragma unroll
    for (int i = 0; i < 4; i++)
        #pragma unroll
        for (int j = 0; j < 4; j++)
            #pragma unroll
            for (int r = 0; r < 4; r++) C[i][j][r] = 0.f;

    const int ar = tid >> 1, ak = (tid & 1) * 8;
    const int bn = tid & 127, bk0 = (tid >> 7) * 8;
    const int cb = coff[bn];

    for (int k0 = 0; k0 < 512; k0 += 16) {
        *(uint4*)&As[ar][ak] = *(const uint4*)&g_MMh[(size_t)(m0+ar)*512 + k0 + ak];
        #pragma unroll
        for (int i = 0; i < 8; i++)
            Bs[bn][bk0+i] = g_CATh[(size_t)cb + (size_t)(k0+bk0+i)*KPAD];
        __syncthreads();
        {
            uint32_t a[4][4], b[4][2];
            #pragma unroll
            for (int mi = 0; mi < 4; mi++) {
                int m = wm*64 + mi*16 + g;
                a[mi][0] = *(const uint32_t*)&As[m][2*t4];
                a[mi][1] = *(const uint32_t*)&As[m+8][2*t4];
                a[mi][2] = *(const uint32_t*)&As[m][2*t4+8];
                a[mi][3] = *(const uint32_t*)&As[m+8][2*t4+8];
            }
            #pragma unroll
            for (int ni = 0; ni < 4; ni++) {
                int n = wn*32 + ni*8 + g;
                b[ni][0] = *(const uint32_t*)&Bs[n][2*t4];
                b[ni][1] = *(const uint32_t*)&Bs[n][2*t4+8];
            }
            #pragma unroll
            for (int mi = 0; mi < 4; mi++)
                #pragma unroll
                for (int ni = 0; ni < 4; ni++)
                    mma_f16(C[mi][ni], a[mi], b[ni]);
        }
        __syncthreads();
    }
    #pragma unroll
    for (int mi = 0; mi < 4; mi++) {
        #pragma unroll
        for (int rr = 0; rr < 2; rr++) {
            int m = m0 + wm*64 + mi*16 + g + rr*8;
            int node  = m & 511;
            int obase = (m < 512) ? 68 : 136;
            size_t rbase = (size_t)node * KPAD + obase;
            #pragma unroll
            for (int ni = 0; ni < 4; ni++) {
                int n = wn*32 + ni*8 + 2*t4;
                g_CATh[coff[n]   + rbase] = __float2half_rn(C[mi][ni][rr*2+0]);
                g_CATh[coff[n+1] + rbase] = __float2half_rn(C[mi][ni][rr*2+1]);
            }
        }
    }
}

// ---------------- FP16 zr gate GEMM: [Z|R] = sigmoid(CAT @ Wzr[p] + bzr[p]) ----------------
__global__ void __launch_bounds__(256) k_gatezr_h(int pfix) {
    const int r0 = blockIdx.x * 128;
    const int p = (pfix >= 0) ? pfix : ((r0 < ROWS_DEC) ? 0 : 1);
    __shared__ __half As[128][24];
    __shared__ __half Bs[128][24];
    const int tid = threadIdx.x;
    const int lane = tid & 31, wid = tid >> 5;
    const int wm = wid & 1, wn = wid >> 1;
    const int g = lane >> 2, t4 = lane & 3;
    float C[4][4][4];
    #pragma unroll
    for (int i = 0; i < 4; i++)
        #pragma unroll
        for (int j = 0; j < 4; j++)
            #pragma unroll
            for (int r = 0; r < 4; r++) C[i][j][r] = 0.f;

    const int ar = tid >> 1, ak = (tid & 1) * 8;
    const int bn = tid & 127, bk0 = (tid >> 7) * 8;
    const __half* Wp = g_Wzrh[p];

    for (int k0 = 0; k0 < KPAD; k0 += 16) {
        *(uint4*)&As[ar][ak] = *(const uint4*)&g_CATh[(size_t)(r0+ar)*KPAD + k0 + ak];
        #pragma unroll
        for (int i = 0; i < 8; i++)
            Bs[bn][bk0+i] = Wp[(k0+bk0+i)*128 + bn];
        __syncthreads();
        {
            uint32_t a[4][4], b[4][2];
            #pragma unroll
            for (int mi = 0; mi < 4; mi++) {
                int m = wm*64 + mi*16 + g;
                a[mi][0] = *(const uint32_t*)&As[m][2*t4];
                a[mi][1] = *(const uint32_t*)&As[m+8][2*t4];
                a[mi][2] = *(const uint32_t*)&As[m][2*t4+8];
                a[mi][3] = *(const uint32_t*)&As[m+8][2*t4+8];
            }
            #pragma unroll
            for (int ni = 0; ni < 4; ni++) {
                int n = wn*32 + ni*8 + g;
                b[ni][0] = *(const uint32_t*)&Bs[n][2*t4];
                b[ni][1] = *(const uint32_t*)&Bs[n][2*t4+8];
            }
            #pragma unroll
            for (int mi = 0; mi < 4; mi++)
                #pragma unroll
                for (int ni = 0; ni < 4; ni++)
                    mma_f16(C[mi][ni], a[mi], b[ni]);
        }
        __syncthreads();
    }
    #pragma unroll
    for (int mi = 0; mi < 4; mi++) {
        #pragma unroll
        for (int rr = 0; rr < 2; rr++) {
            int row = r0 + wm*64 + mi*16 + g + rr*8;
            #pragma unroll
            for (int ni = 0; ni < 4; ni++) {
                #pragma unroll
                for (int q = 0; q < 2; q++) {
                    int col = wn*32 + ni*8 + 2*t4 + q;
                    float v = sigm(C[mi][ni][rr*2+q] + g_bzr[p][col]);
                    if (col < 64) g_z[(size_t)row*64 + col]      = v;
                    else          g_r[(size_t)row*64 + col - 64] = v;
                }
            }
        }
    }
}

// ---------------- FP16 C gate GEMM + H update ----------------
__global__ void __launch_bounds__(256) k_gatec_h(int pfix, int dec) {
    const int r0 = blockIdx.x * 128;
    const int p = (pfix >= 0) ? pfix : ((r0 < ROWS_DEC) ? 0 : 1);
    float* H = dec ? g_Hdec : g_H;
    __shared__ __half As[128][24];
    __shared__ __half Bs[64][24];
    const int tid = threadIdx.x;
    const int lane = tid & 31, wid = tid >> 5;
    const int wm = wid & 3, wn = wid >> 2;        // 4 m-warps x 2 n-warps (32x32)
    const int g = lane >> 2, t4 = lane & 3;
    float C[2][4][4];
    #pragma unroll
    for (int i = 0; i < 2; i++)
        #pragma unroll
        for (int j = 0; j < 4; j++)
            #pragma unroll
            for (int r = 0; r < 4; r++) C[i][j][r] = 0.f;

    const int ar = tid >> 1, ak = (tid & 1) * 8;
    const int bn = tid & 63, bk0 = (tid >> 6) * 4;
    const __half* Wp = g_Wch[p];

    for (int k0 = 0; k0 < KPAD; k0 += 16) {
        *(uint4*)&As[ar][ak] = *(const uint4*)&g_CATh[(size_t)(r0+ar)*KPAD + k0 + ak];
        #pragma unroll
        for (int i = 0; i < 4; i++)
            Bs[bn][bk0+i] = Wp[(k0+bk0+i)*64 + bn];
        __syncthreads();
        {
            uint32_t a[2][4], b[4][2];
            #pragma unroll
            for (int mi = 0; mi < 2; mi++) {
                int m = wm*32 + mi*16 + g;
                a[mi][0] = *(const uint32_t*)&As[m][2*t4];
                a[mi][1] = *(const uint32_t*)&As[m+8][2*t4];
                a[mi][2] = *(const uint32_t*)&As[m][2*t4+8];
                a[mi][3] = *(const uint32_t*)&As[m+8][2*t4+8];
            }
            #pragma unroll
            for (int ni = 0; ni < 4; ni++) {
                int n = wn*32 + ni*8 + g;
                b[ni][0] = *(const uint32_t*)&Bs[n][2*t4];
                b[ni][1] = *(const uint32_t*)&Bs[n][2*t4+8];
            }
            #pragma unroll
            for (int mi = 0; mi < 2; mi++)
                #pragma unroll
                for (int ni = 0; ni < 4; ni++)
                    mma_f16(C[mi][ni], a[mi], b[ni]);
        }
        __syncthreads();
    }
    #pragma unroll
    for (int mi = 0; mi < 2; mi++) {
        #pragma unroll
        for (int rr = 0; rr < 2; rr++) {
            int row = r0 + wm*32 + mi*16 + g + rr*8;
            #pragma unroll
            for (int ni = 0; ni < 4; ni++) {
                #pragma unroll
                for (int q = 0; q < 2; q++) {
                    int col = wn*32 + ni*8 + 2*t4 + q;
                    float c = tanhf(C[mi][ni][rr*2+q] + g_bc[p][col]);
                    float z = g_z[(size_t)row*64 + col];
                    float h = H[(size_t)row*64 + col];
                    H[(size_t)row*64 + col] = z*h + (1.f - z)*c;
                }
            }
        }
    }
}

// ---------------- mix GEMM (fp32, one call) ----------------
__global__ void __launch_bounds__(256) k_mix() {
    const int r0 = blockIdx.x * 128;
    __shared__ float As[8][128];
    __shared__ float Bs[8][64];
    const int tid = threadIdx.x;
    float acc[8][4];
    #pragma unroll
    for (int i = 0; i < 8; i++)
        #pragma unroll
        for (int j = 0; j < 4; j++) acc[i][j] = 0.f;

    const int arow = tid >> 1, acol = (tid & 1) * 4;
    const int tx = tid & 15, ty = tid >> 4;

    for (int k0 = 0; k0 < 128; k0 += 8) {
        int row = r0 + arow;
        const float* src = (k0 < 64) ? &g_H[(size_t)row*64 + k0 + acol]
                                     : &g_H[((size_t)row + ROWS_DEC)*64 + (k0 - 64) + acol];
        float4 av = *(const float4*)src;
        As[acol+0][arow] = av.x; As[acol+1][arow] = av.y;
        As[acol+2][arow] = av.z; As[acol+3][arow] = av.w;
        #pragma unroll
        for (int r = 0; r < 2; r++) {
            int ii = tid + r*256;
            int k = ii >> 6, j = ii & 63;
            Bs[k][j] = g_Wmix[(k0+k)*64 + j];
        }
        __syncthreads();
        #pragma unroll
        for (int kk = 0; kk < 8; kk++) {
            float4 a0 = *(const float4*)&As[kk][ty*8];
            float4 a1 = *(const float4*)&As[kk][ty*8+4];
            float4 b0 = *(const float4*)&Bs[kk][tx*4];
            float aa[8] = {a0.x,a0.y,a0.z,a0.w,a1.x,a1.y,a1.z,a1.w};
            float bb[4] = {b0.x,b0.y,b0.z,b0.w};
            #pragma unroll
            for (int i = 0; i < 8; i++)
                #pragma unroll
                for (int j = 0; j < 4; j++)
                    acc[i][j] += aa[i]*bb[j];
        }
        __syncthreads();
    }
    #pragma unroll
    for (int i = 0; i < 8; i++) {
        int row = r0 + ty*8 + i;
        #pragma unroll
        for (int j = 0; j < 4; j++) {
            int col = tx*4 + j;
            g_Hdec[row*64 + col] = acc[i][j] + g_bmix[col];
        }
    }
}

// ---------------- decoder FC + output scatter + next xt ----------------
__global__ void k_fc(const float* __restrict__ Wfc, const float* __restrict__ bfc,
                     float* __restrict__ out, int t) {
    int row = blockIdx.x*blockDim.x + threadIdx.x;
    if (row >= ROWS_DEC) return;
    int b = row >> 9, n = row & 511;
    float a0 = bfc[0], a1 = bfc[1], a2 = bfc[2];
    const float* h = &g_Hdec[(size_t)row*64];
    #pragma unroll 8
    for (int k = 0; k < 64; k++) {
        float hv = h[k];
        a0 += hv * Wfc[k*3+0];
        a1 += hv * Wfc[k*3+1];
        a2 += hv * Wfc[k*3+2];
    }
    float av[3] = {a0, a1, a2};
    #pragma unroll
    for (int d = 0; d < 3; d++) {
        int L = 3*t + d;
        int dp = L / 12, tp = L % 12;
        out[((b*3+dp)*512 + n)*12 + tp] = av[d];
        g_xt_dec[row*4 + d] = av[d];
    }
    if (t + 1 < 12) g_xt_dec[row*4 + 3] = g_tod[b*12 + t + 1];
}

// ---------------- launch ----------------
extern "C" void kernel_launch(void* const* d_in, const int* in_sizes, int n_in,
                              void* d_out, int out_size) {
    const float* x   = (const float*)d_in[0];
    const float* st  = (const float*)d_in[2];
    const float* A   = (const float*)d_in[3];
    const float* Wg  = (const float*)d_in[4];
    const float* bg  = (const float*)d_in[5];
    const float* Wm  = (const float*)d_in[6];
    const float* bm  = (const float*)d_in[7];
    const float* Wi  = (const float*)d_in[8];
    const float* bi  = (const float*)d_in[9];
    const float* Wfc = (const float*)d_in[10];
    const float* bfc = (const float*)d_in[11];
    float* out = (float*)d_out;

    // prep
    k_rowsum<<<512, 128>>>(A);
    k_P<<<1024, 256>>>(A);
    k_M2<<<1024, 256>>>();
    k_weights<<<(3*204*128 + 3*204*64 + 3*128 + 3*64 + 255)/256, 256>>>(Wg, bg);
    k_mixw<<<(4160 + 255)/256, 256>>>(Wi, bi, Wm, bm);
    k_tod<<<3, 256>>>(st);
    k_xt_enc<<<(6*ROWS_ENC*4)/256, 256>>>(x, st);
    k_init_state<<<(ROWS_ENC*64 + ROWS_DEC*4)/256, 256>>>();

    // encoders (D + A batched: 128 batch-slices)
    for (int t = 0; t < 6; t++) {
        k_comb<<<((size_t)ROWS_ENC*68 + 255)/256, 256>>>(t, 0);
        k_graph_h<<<dim3(68, 8), 256>>>();
        k_gatezr_h<<<ROWS_ENC/128, 256>>>(-1);
        k_temp<<<(ROWS_ENC*64)/256, 256>>>(0);
        k_graph_h<<<dim3(68, 8), 256>>>();
        k_gatec_h<<<ROWS_ENC/128, 256>>>(-1, 0);
    }

    // mix -> decoder initial H
    k_mix<<<ROWS_DEC/128, 256>>>();

    // decoder
    for (int t = 0; t < 12; t++) {
        k_comb<<<((size_t)ROWS_DEC*68 + 255)/256, 256>>>(0, 1);
        k_graph_h<<<dim3(34, 8), 256>>>();
        k_gatezr_h<<<ROWS_DEC/128, 256>>>(2);
        k_temp<<<(ROWS_DEC*64)/256, 256>>>(1);
        k_graph_h<<<dim3(34, 8), 256>>>();
        k_gatec_h<<<ROWS_DEC/128, 256>>>(2, 1);
        k_fc<<<ROWS_DEC/256, 256>>>(Wfc, bfc, out, t);
    }
}